// round 4
// baseline (speedup 1.0000x reference)
#include <cuda_runtime.h>
#include <cuda_bf16.h>

// LoongSpike fractional-SSM Vandermonde kernel, round 4.
// K[h,l] = 2*Re( sum_n C_disc[h,n] * r_n^l ),  r_n = exp(dtA[h,n]).
// Real second-order recurrence x_{l+1} = p x_l + q x_{l-1} (p=2Re r, q=-|r|^2),
// two states packed per f32x2 op.
// Round-4: 64-thread blocks (2 warps) covering 64 chunks x 16 l; one state per
// thread in phase 1 with tiered (serial-16 + 3x doubling) W0 fill; seeds
// (x0,x1) and coeffs (p,q) precomputed in smem to shrink phase-2 overhead.

#define Hh      512
#define NSTc    32
#define LCc     16      // l-elements per thread/chunk
#define NCH     64      // chunks per block -> block covers 1024 l
#define NSTATES 64
#define GRPS    8       // 8 groups x 4 packed pairs = 64 states
#define NPAIR   4

typedef unsigned long long u64;

#define MUL2(d, a, b) \
    asm("mul.rn.f32x2 %0, %1, %2;" : "=l"(d) : "l"(a), "l"(b))
#define ADD2(d, a, b) \
    asm("add.rn.f32x2 %0, %1, %2;" : "=l"(d) : "l"(a), "l"(b))
#define FMA2(d, a, b, c) \
    asm("fma.rn.f32x2 %0, %1, %2, %3;" : "=l"(d) : "l"(a), "l"(b), "l"(c))
#define PACK2(d, lo, hi) \
    asm("mov.b64 %0, {%1, %2};" : "=l"(d) : "r"(__float_as_uint(lo)), "r"(__float_as_uint(hi)))
#define UNPACK2(lo, hi, v) \
    asm("mov.b64 {%0, %1}, %2;" : "=r"(lo), "=r"(hi) : "l"(v))

__global__ __launch_bounds__(64) void loong_spike_kernel(
    const float* __restrict__ C_real,      // [1, H, NST, 2]
    const float* __restrict__ log_dt,      // [H]
    const float* __restrict__ log_A_real,  // [H, NST]
    const float* __restrict__ A_imag,      // [H, NST]
    const float* __restrict__ omega_logit, // [2]
    const float* __restrict__ eta_logit,   // [2]
    float* __restrict__ out,               // [1, H, L]
    int L)
{
    __shared__ float2 W0[NSTATES][NCH + 1];   // (x0, x1) seeds, padded pitch
    __shared__ float2 PQ[NSTATES];            // (p, q) per state

    const int tid = threadIdx.x;              // 0..63
    const int h   = blockIdx.y;
    const int bx  = blockIdx.x;
    const int l0_base = bx * (NCH * LCc);

    // ---------------- Phase 1: one state per thread -------------------------
    {
        const int n   = tid;                  // state index 0..63
        const int s   = n >> 5;               // m index
        const int nst = n & 31;

        const float dt  = expf(log_dt[h]);
        const float Are = -expf(log_A_real[h * NSTc + nst]);
        const float Aim = A_imag[h * NSTc + nst];

        const float ol = omega_logit[s];
        const float el = eta_logit[s];
        const float omega = 1e-6f + (1.0f / (1.0f + expf(-ol))) * (100.0f - 1e-6f);
        const float eta   = 1e-6f + (1.0f / (1.0f + expf(-el))) * (10.0f  - 1e-6f);

        const float Afr = -omega + eta * Are;     // A_frac
        const float Afi = eta * Aim;
        const float Cre = eta * C_real[(h * NSTc + nst) * 2 + 0];  // C_frac
        const float Cim = eta * C_real[(h * NSTc + nst) * 2 + 1];

        const float dr = Afr * dt;                // dtA
        const float di = Afi * dt;

        // r = exp(dtA)
        float er, sn, cs;
        er = expf(dr);
        sincosf(di, &sn, &cs);
        const float rre = er * cs;
        const float rim = er * sn;

        // C_disc
        float Cdre, Cdim;
        const float mag2 = Afr * Afr + Afi * Afi;
        if (mag2 < 1e-12f) {
            Cdre = Cre * dt;
            Cdim = Cim * dt;
        } else {
            const float nre = rre - 1.0f, nim = rim;
            const float tre = Cre * nre - Cim * nim;
            const float tim = Cre * nim + Cim * nre;
            const float dre = Afr + 1e-8f, dim = Afi;
            const float inv = 1.0f / (dre * dre + dim * dim);
            Cdre = (tre * dre + tim * dim) * inv;
            Cdim = (tim * dre - tre * dim) * inv;
        }

        // w at block start: w = C_disc * exp(dtA * l0_base)
        const float p0 = (float)l0_base;
        float ssn, scs;
        const float serx = expf(dr * p0);
        sincosf(di * p0, &ssn, &scs);
        const float Sre = serx * scs, Sim = serx * ssn;
        float w0re = Cdre * Sre - Cdim * Sim;
        float w0im = Cdre * Sim + Cdim * Sre;

        // per-chunk ratio R = exp(dtA * LCc), tier ratio R16 = exp(dtA * 16*LCc)
        float sR, cR, s16, c16;
        const float eR = expf(dr * (float)LCc);
        sincosf(di * (float)LCc, &sR, &cR);
        const float Rre = eR * cR, Rim = eR * sR;
        const float e16 = expf(dr * (float)(16 * LCc));
        sincosf(di * (float)(16 * LCc), &s16, &c16);
        const float R16re = e16 * c16, R16im = e16 * s16;

        // coefficients p = 2 Re(r), q = -|r|^2
        PQ[n] = make_float2(2.0f * rre, -(rre * rre + rim * rim));

        // 16 serial chunk values in registers, then 3 doubling tiers
        float wr[16], wi[16];
        wr[0] = w0re; wi[0] = w0im;
        #pragma unroll
        for (int i = 1; i < 16; ++i) {
            wr[i] = wr[i-1] * Rre - wi[i-1] * Rim;
            wi[i] = wr[i-1] * Rim + wi[i-1] * Rre;
        }
        #pragma unroll
        for (int tier = 0; tier < 4; ++tier) {
            #pragma unroll
            for (int i = 0; i < 16; ++i) {
                const int ci = tier * 16 + i;
                // seeds: x0 = Re(w), x1 = Re(w * r)
                const float x0 = wr[i];
                const float x1 = wr[i] * rre - wi[i] * rim;
                W0[n][ci] = make_float2(x0, x1);
                if (tier < 3) {
                    const float t1 = wr[i] * R16re - wi[i] * R16im;
                    const float t2 = wr[i] * R16im + wi[i] * R16re;
                    wr[i] = t1; wi[i] = t2;
                }
            }
        }
    }
    __syncthreads();

    // ---------------- Phase 2: packed real second-order recurrence ---------
    const int ci = tid;
    const int l0 = l0_base + ci * LCc;
    if (l0 >= L) return;

    u64 acc2[LCc];
    #pragma unroll
    for (int l = 0; l < LCc; ++l) acc2[l] = 0ull;

    #pragma unroll 1
    for (int g = 0; g < GRPS; ++g) {
        u64 prev2[NPAIR], cur2[NPAIR], p2[NPAIR], q2[NPAIR];
        #pragma unroll
        for (int pr = 0; pr < NPAIR; ++pr) {
            const int n0 = g * (2 * NPAIR) + 2 * pr;
            const float2 a  = W0[n0][ci];        // (x0, x1) state a
            const float2 b  = W0[n0 + 1][ci];    // (x0, x1) state b
            const float2 pa = PQ[n0];            // broadcast
            const float2 pb = PQ[n0 + 1];
            PACK2(prev2[pr], a.x, b.x);
            PACK2(cur2[pr],  a.y, b.y);
            PACK2(p2[pr],    pa.x, pb.x);
            PACK2(q2[pr],    pa.y, pb.y);
        }
        #pragma unroll
        for (int pr = 0; pr < NPAIR; ++pr)
            ADD2(acc2[0], acc2[0], prev2[pr]);
        #pragma unroll
        for (int l = 1; l < LCc; ++l) {
            #pragma unroll
            for (int pr = 0; pr < NPAIR; ++pr) {
                ADD2(acc2[l], acc2[l], cur2[pr]);
                u64 t, nx;
                MUL2(t, q2[pr], prev2[pr]);          // q * x_{l-1}
                FMA2(nx, p2[pr], cur2[pr], t);       // x_{l+1} = p*x_l + q*x_{l-1}
                prev2[pr] = cur2[pr];
                cur2[pr]  = nx;
            }
        }
    }

    float* op = out + (size_t)h * L + l0;
    if (l0 + LCc <= L) {
        float res[LCc];
        #pragma unroll
        for (int l = 0; l < LCc; ++l) {
            unsigned int lo, hi;
            UNPACK2(lo, hi, acc2[l]);
            res[l] = 2.0f * (__uint_as_float(lo) + __uint_as_float(hi));
        }
        #pragma unroll
        for (int l = 0; l < LCc; l += 4) {
            *reinterpret_cast<float4*>(op + l) =
                make_float4(res[l], res[l + 1], res[l + 2], res[l + 3]);
        }
    } else {
        for (int l = 0; l < LCc && l0 + l < L; ++l) {
            unsigned int lo, hi;
            UNPACK2(lo, hi, acc2[l]);
            op[l] = 2.0f * (__uint_as_float(lo) + __uint_as_float(hi));
        }
    }
}

extern "C" void kernel_launch(void* const* d_in, const int* in_sizes, int n_in,
                              void* d_out, int out_size) {
    const float* C_real      = (const float*)d_in[0];
    const float* log_dt      = (const float*)d_in[1];
    const float* log_A_real  = (const float*)d_in[2];
    const float* A_imag      = (const float*)d_in[3];
    const float* omega_logit = (const float*)d_in[4];
    const float* eta_logit   = (const float*)d_in[5];
    float* out = (float*)d_out;

    const int L  = out_size / Hh;                       // CH == 1
    const int lpb = NCH * LCc;                          // 1024 l per block
    const int gx  = (L + lpb - 1) / lpb;

    dim3 grid(gx, Hh);
    loong_spike_kernel<<<grid, NSTATES>>>(C_real, log_dt, log_A_real, A_imag,
                                          omega_logit, eta_logit, out, L);
}